// round 14
// baseline (speedup 1.0000x reference)
#include <cuda_runtime.h>
#include <math.h>

#define N_TOK 1024
#define Dm 512
#define Kf 128
#define Sq 512
#define DK 64
#define NSPLIT 4
#define ATTN_SMEM (3 * 64 * 68 * 4)

// ---------------- scratch ---------------------------------------------------
__device__ float g_feat[(N_TOK + 4 * Dm) * Kf];
__device__ float g_R[N_TOK + 4 * Dm];
__device__ float g_Rcf[N_TOK];
__device__ float g_QKV[3 * N_TOK * Dm];
__device__ float g_ctx[N_TOK * Dm];
__device__ float g_pout[NSPLIT * 16 * Sq * DK];
__device__ float g_pml[NSPLIT * 16 * Sq * 2];
__device__ float g_cfp[8][N_TOK * Kf];
__device__ float g_cf[N_TOK * Kf];

// ---------------- feature GEMM: feat = [x;Pq;Pk;Pv;Po] @ omega --------------
__global__ __launch_bounds__(256) void feat_gemm(
    const float* __restrict__ x,  const float* __restrict__ Pq,
    const float* __restrict__ Pk, const float* __restrict__ Pv,
    const float* __restrict__ Po, const float* __restrict__ omega,
    float* __restrict__ feat)
{
    __shared__ float As[32][36];
    __shared__ float Bs[32][68];
    int tx = threadIdx.x, ty = threadIdx.y;
    int tid = ty * 16 + tx;
    int bm = blockIdx.y * 32, bn = blockIdx.x * 64;

    const float* A;
    int row0;
    if (bm < N_TOK) { A = x; row0 = bm; }
    else {
        int s = (bm - N_TOK) >> 9;
        const float* Ps[4] = {Pq, Pk, Pv, Po};
        A = Ps[s]; row0 = (bm - N_TOK) & 511;
    }

    float acc[2][4] = {};
    for (int k0 = 0; k0 < Dm; k0 += 32) {
#pragma unroll
        for (int l = 0; l < 4; l++) {
            int e = tid + l * 256;
            int i = e >> 5, j = e & 31;
            As[j][i] = A[(size_t)(row0 + i) * Dm + k0 + j];
        }
#pragma unroll
        for (int l = 0; l < 8; l++) {
            int e = tid + l * 256;
            int kk = e >> 6, j = e & 63;
            Bs[kk][j] = omega[(size_t)(k0 + kk) * Kf + bn + j];
        }
        __syncthreads();
#pragma unroll
        for (int k = 0; k < 32; k++) {
            float2 a2 = *(const float2*)&As[k][ty * 2];
            float4 b4 = *(const float4*)&Bs[k][tx * 4];
            acc[0][0] = fmaf(a2.x, b4.x, acc[0][0]);
            acc[0][1] = fmaf(a2.x, b4.y, acc[0][1]);
            acc[0][2] = fmaf(a2.x, b4.z, acc[0][2]);
            acc[0][3] = fmaf(a2.x, b4.w, acc[0][3]);
            acc[1][0] = fmaf(a2.y, b4.x, acc[1][0]);
            acc[1][1] = fmaf(a2.y, b4.y, acc[1][1]);
            acc[1][2] = fmaf(a2.y, b4.z, acc[1][2]);
            acc[1][3] = fmaf(a2.y, b4.w, acc[1][3]);
        }
        __syncthreads();
    }
#pragma unroll
    for (int i = 0; i < 2; i++)
#pragma unroll
        for (int j = 0; j < 4; j++)
            feat[(size_t)(bm + ty * 2 + i) * Kf + bn + tx * 4 + j] = acc[i][j];
}

// ---------------- split-K GEMM (K split 8) ----------------------------------
__global__ __launch_bounds__(256) void gemm_split(
    const float* __restrict__ A, const float* __restrict__ B,
    float* __restrict__ Cp)
{
    __shared__ float As[32][68];
    __shared__ float Bs[32][68];
    int tx = threadIdx.x, ty = threadIdx.y;
    int tid = ty * 16 + tx;
    int bm = blockIdx.y * 64, bn = blockIdx.x * 64;
    int kbase = blockIdx.z * 64;
    float* C = Cp + (size_t)blockIdx.z * N_TOK * Kf;
    float acc[4][4] = {};
    for (int k0 = kbase; k0 < kbase + 64; k0 += 32) {
#pragma unroll
        for (int l = 0; l < 8; l++) {
            int e = tid + l * 256;
            int i = e >> 5, j = e & 31;
            As[j][i] = A[(size_t)(bm + i) * Dm + k0 + j];
        }
#pragma unroll
        for (int l = 0; l < 8; l++) {
            int e = tid + l * 256;
            int kk = e >> 6, j = e & 63;
            Bs[kk][j] = B[(size_t)(k0 + kk) * Kf + bn + j];
        }
        __syncthreads();
#pragma unroll
        for (int k = 0; k < 32; k++) {
            float4 a4 = *(const float4*)&As[k][ty * 4];
            float4 b4 = *(const float4*)&Bs[k][tx * 4];
            float av[4] = {a4.x, a4.y, a4.z, a4.w};
            float bv[4] = {b4.x, b4.y, b4.z, b4.w};
#pragma unroll
            for (int i = 0; i < 4; i++)
#pragma unroll
                for (int j = 0; j < 4; j++)
                    acc[i][j] = fmaf(av[i], bv[j], acc[i][j]);
        }
        __syncthreads();
    }
#pragma unroll
    for (int i = 0; i < 4; i++)
#pragma unroll
        for (int j = 0; j < 4; j++)
            C[(size_t)(bm + ty * 4 + i) * Kf + bn + tx * 4 + j] = acc[i][j];
}

// add 8 split-K partials AND emit row relu-sums (warp == one 128-float row)
__global__ __launch_bounds__(256) void add8_relu(
    const float* __restrict__ Cp, float* __restrict__ C,
    float* __restrict__ Rcf)
{
    int idx = blockIdx.x * 256 + threadIdx.x;
    const size_t n = (size_t)N_TOK * Kf;
    float4 r = ((const float4*)Cp)[idx];
#pragma unroll
    for (int z = 1; z < 8; z++) {
        float4 a = ((const float4*)(Cp + (size_t)z * n))[idx];
        r.x += a.x; r.y += a.y; r.z += a.z; r.w += a.w;
    }
    ((float4*)C)[idx] = r;
    float s = fmaxf(r.x, 0.f) + fmaxf(r.y, 0.f) + fmaxf(r.z, 0.f) + fmaxf(r.w, 0.f);
#pragma unroll
    for (int o = 16; o; o >>= 1) s += __shfl_xor_sync(0xffffffffu, s, o);
    if ((threadIdx.x & 31) == 0) Rcf[idx >> 5] = s;
}

// ---------------- row relu-sums (feat) ---------------------------------------
__global__ __launch_bounds__(256) void rowrelu(const float* __restrict__ f,
                                               float* __restrict__ R)
{
    int row = blockIdx.x * 8 + threadIdx.y;
    int lane = threadIdx.x;
    float4 v = ((const float4*)(f + (size_t)row * Kf))[lane];
    float s = fmaxf(v.x, 0.f) + fmaxf(v.y, 0.f) + fmaxf(v.z, 0.f) + fmaxf(v.w, 0.f);
#pragma unroll
    for (int o = 16; o; o >>= 1) s += __shfl_xor_sync(0xffffffffu, s, o);
    if (lane == 0) R[row] = s;
}

// ---------------- Tversky 64x64 tile, min-trick, 3 blocks/SM -----------------
__device__ __forceinline__ void tversky_tile(
    const float* __restrict__ xf, const float* __restrict__ pf,
    const float* __restrict__ Rx, const float* __restrict__ Rp,
    float th, float al, float be, int bn, int bo,
    float* __restrict__ out, int ldo)
{
    __shared__ float sxa[16][68], sxA[16][68], sxW[16][68];
    __shared__ float spa[16][68], spP[16][68], spW[16][68];
    int tx = threadIdx.x, ty = threadIdx.y;
    int tid = ty * 16 + tx;
    float acc[4][4] = {};
    for (int k0 = 0; k0 < Kf; k0 += 16) {
#pragma unroll
        for (int l = 0; l < 4; l++) {
            int e = tid + l * 256;
            int i = e >> 4, j = e & 15;
            float a = xf[(size_t)(bn + i) * Kf + k0 + j];
            sxa[j][i] = a;
            sxA[j][i] = th * fmaxf(a, 0.f);
            sxW[j][i] = (a > 0.f) ? al : 0.f;
            float p = pf[(size_t)(bo + i) * Kf + k0 + j];
            spa[j][i] = p;
            spP[j][i] = fmaxf(p, 0.f);
            spW[j][i] = (p > 0.f) ? be : 0.f;
        }
        __syncthreads();
#pragma unroll
        for (int k = 0; k < 16; k++) {
            float4 a4 = *(const float4*)&sxa[k][ty * 4];
            float4 A4 = *(const float4*)&sxA[k][ty * 4];
            float4 w4 = *(const float4*)&sxW[k][ty * 4];
            float4 p4 = *(const float4*)&spa[k][tx * 4];
            float4 P4 = *(const float4*)&spP[k][tx * 4];
            float4 v4 = *(const float4*)&spW[k][tx * 4];
            float av[4] = {a4.x, a4.y, a4.z, a4.w};
            float Av[4] = {A4.x, A4.y, A4.z, A4.w};
            float wv[4] = {w4.x, w4.y, w4.z, w4.w};
            float pv[4] = {p4.x, p4.y, p4.z, p4.w};
            float Pv[4] = {P4.x, P4.y, P4.z, P4.w};
            float vv[4] = {v4.x, v4.y, v4.z, v4.w};
#pragma unroll
            for (int i = 0; i < 4; i++)
#pragma unroll
                for (int j = 0; j < 4; j++) {
                    float m = fminf(av[i], pv[j]);
                    float t = acc[i][j];
                    t = fmaf(Av[i], Pv[j], t);
                    t = fmaf(wv[i], m, t);
                    t = fmaf(vv[j], m, t);
                    acc[i][j] = t;
                }
        }
        __syncthreads();
    }
    float rx[4], rp[4];
#pragma unroll
    for (int i = 0; i < 4; i++) rx[i] = al * Rx[bn + ty * 4 + i];
#pragma unroll
    for (int j = 0; j < 4; j++) rp[j] = be * Rp[bo + tx * 4 + j];
#pragma unroll
    for (int i = 0; i < 4; i++)
#pragma unroll
        for (int j = 0; j < 4; j++)
            out[(size_t)(bn + ty * 4 + i) * ldo + bo + tx * 4 + j] =
                acc[i][j] - rx[i] - rp[j];
}

__global__ __launch_bounds__(256, 3) void tversky_qkv(
    const float* __restrict__ feat, const float* __restrict__ R,
    const float* __restrict__ tab, float* __restrict__ qkv)
{
    int z = blockIdx.z;
    const float* pf = feat + (size_t)(N_TOK + z * Dm) * Kf;
    const float* Rp = R + N_TOK + z * Dm;
    const float* t3 = tab + z * 3;
    float* out = qkv + (size_t)z * N_TOK * Dm;
    tversky_tile(feat, pf, R, Rp, t3[0], t3[1], t3[2],
                 blockIdx.y * 64, blockIdx.x * 64, out, Dm);
}

__global__ __launch_bounds__(256, 3) void tversky_out(
    const float* __restrict__ cf, const float* __restrict__ Rcf,
    const float* __restrict__ feat, const float* __restrict__ R,
    const float* __restrict__ tab, float* __restrict__ out)
{
    const float* pf = feat + (size_t)(N_TOK + 3 * Dm) * Kf;
    const float* Rp = R + N_TOK + 3 * Dm;
    tversky_tile(cf, pf, Rcf, Rp, tab[9], tab[10], tab[11],
                 blockIdx.y * 64, blockIdx.x * 64, out, Dm);
}

// ---------------- flash attention, 4x4 micro-tile, kv-split 4, 3 blk/SM ------
// Grid (8 q-tiles of 64, 16 z, 4 kv-splits of 128 k = 2 chunks).
// Dynamic smem: Qs[64][68] | Ks[64][68] | Pst[64][68]  (52224 bytes)
__global__ __launch_bounds__(256, 3) void attn_part(
    const float* __restrict__ Q, const float* __restrict__ Km,
    const float* __restrict__ V, const int* __restrict__ mask,
    float* __restrict__ pout, float* __restrict__ pml)
{
    extern __shared__ float smem[];
    float (*Qs)[68]  = (float (*)[68])smem;                 // [d][q]
    float (*Ks)[68]  = (float (*)[68])(smem + 64 * 68);     // [d][k] / [k][d]
    float (*Pst)[68] = (float (*)[68])(smem + 2 * 64 * 68); // probs^T [k][q]
    int z = blockIdx.y;
    int sp = blockIdx.z;
    int b = z >> 3, h = z & 7;
    const float* Qg = Q  + (size_t)b * Sq * Dm + h * DK;
    const float* Kg = Km + (size_t)b * Sq * Dm + h * DK;
    const float* Vg = V  + (size_t)b * Sq * Dm + h * DK;
    const int*   mg = mask + (size_t)b * Sq * Sq;
    int bq = blockIdx.x * 64;
    int tx = threadIdx.x, ty = threadIdx.y;
    int tid = ty * 16 + tx;

#pragma unroll
    for (int l = 0; l < 16; l++) {         // Qs: 64q x 64d
        int e = tid + l * 256;
        int m = e >> 6, d = e & 63;
        Qs[d][m] = Qg[(size_t)(bq + m) * Dm + d];
    }

    float out[4][4] = {};
    float mr[4] = {-INFINITY, -INFINITY, -INFINITY, -INFINITY};
    float lr[4] = {};

    for (int kc = 0; kc < 2; kc++) {
        int bk = sp * 128 + kc * 64;
#pragma unroll
        for (int l = 0; l < 16; l++) {     // Ks[d][k]
            int e = tid + l * 256;
            int kk = e >> 6, d = e & 63;
            Ks[d][kk] = Kg[(size_t)(bk + kk) * Dm + d];
        }
        __syncthreads();

        float S[4][4] = {};
#pragma unroll
        for (int d = 0; d < 64; d++) {
            float4 q4 = *(const float4*)&Qs[d][ty * 4];
            float4 k4 = *(const float4*)&Ks[d][tx * 4];
            float qv[4] = {q4.x, q4.y, q4.z, q4.w};
            float kv[4] = {k4.x, k4.y, k4.z, k4.w};
#pragma unroll
            for (int i = 0; i < 4; i++)
#pragma unroll
                for (int j = 0; j < 4; j++)
                    S[i][j] = fmaf(qv[i], kv[j], S[i][j]);
        }
        __syncthreads();                   // done reading Ks

        // mask
#pragma unroll
        for (int i = 0; i < 4; i++) {
            int row = bq + ty * 4 + i;
            int4 m4 = *(const int4*)&mg[(size_t)row * Sq + bk + tx * 4];
            if (m4.x == 0) S[i][0] = -INFINITY;
            if (m4.y == 0) S[i][1] = -INFINITY;
            if (m4.z == 0) S[i][2] = -INFINITY;
            if (m4.w == 0) S[i][3] = -INFINITY;
        }

        // per-row chunk max across 16 tx lanes (half-warp)
        float cm[4], sc[4], cs[4];
#pragma unroll
        for (int i = 0; i < 4; i++) {
            float c = fmaxf(fmaxf(S[i][0], S[i][1]), fmaxf(S[i][2], S[i][3]));
#pragma unroll
            for (int o = 8; o; o >>= 1)
                c = fmaxf(c, __shfl_xor_sync(0xffffffffu, c, o));
            cm[i] = fmaxf(mr[i], c);
            sc[i] = __expf((mr[i] - cm[i]) * 0.125f);
            mr[i] = cm[i];
        }

        // P = exp((S - m)/8); transposed store; chunk sums
#pragma unroll
        for (int i = 0; i < 4; i++) {
            float p0 = __expf((S[i][0] - cm[i]) * 0.125f);
            float p1 = __expf((S[i][1] - cm[i]) * 0.125f);
            float p2 = __expf((S[i][2] - cm[i]) * 0.125f);
            float p3 = __expf((S[i][3] - cm[i]) * 0.125f);
            S[i][0] = p0; S[i][1] = p1; S[i][2] = p2; S[i][3] = p3;
            cs[i] = p0 + p1 + p2 + p3;
        }
#pragma unroll
        for (int i = 0; i < 4; i++) {
            float s = cs[i];
#pragma unroll
            for (int o = 8; o; o >>= 1)
                s += __shfl_xor_sync(0xffffffffu, s, o);
            lr[i] = lr[i] * sc[i] + s;
#pragma unroll
            for (int j = 0; j < 4; j++) out[i][j] *= sc[i];
        }
#pragma unroll
        for (int j = 0; j < 4; j++)        // Pst[k][q]: 4 STS.128
            *(float4*)&Pst[tx * 4 + j][ty * 4] =
                make_float4(S[0][j], S[1][j], S[2][j], S[3][j]);

#pragma unroll
        for (int l = 0; l < 16; l++) {     // Vs[k][d] into Ks
            int e = tid + l * 256;
            int kk = e >> 6, d = e & 63;
            Ks[kk][d] = Vg[(size_t)(bk + kk) * Dm + d];
        }
        __syncthreads();                   // Pst + V visible

#pragma unroll
        for (int k = 0; k < 64; k++) {
            float4 p4 = *(const float4*)&Pst[k][ty * 4];
            float4 v4 = *(const float4*)&Ks[k][tx * 4];
            float pv[4] = {p4.x, p4.y, p4.z, p4.w};
            float vv[4] = {v4.x, v4.y, v4.z, v4.w};
#pragma unroll
            for (int i = 0; i < 4; i++)
#pragma unroll
                for (int j = 0; j < 4; j++)
                    out[i][j] = fmaf(pv[i], vv[j], out[i][j]);
        }
        __syncthreads();                   // done reading Ks/Pst
    }

    // write unnormalized partials
    float* po = pout + ((size_t)(sp * 16 + z) * Sq) * DK;
#pragma unroll
    for (int i = 0; i < 4; i++) {
        int row = bq + ty * 4 + i;
        *(float4*)&po[(size_t)row * DK + tx * 4] =
            make_float4(out[i][0], out[i][1], out[i][2], out[i][3]);
        if (tx == 0) {
            float* pm = pml + ((size_t)(sp * 16 + z) * Sq) * 2;
            pm[row * 2] = mr[i]; pm[row * 2 + 1] = lr[i];
        }
    }
}

// combine NSPLIT kv-split partials -> ctx. Block (64, 4).
__global__ __launch_bounds__(256) void attn_combine(
    const float* __restrict__ pout, const float* __restrict__ pml,
    float* __restrict__ ctx)
{
    int row = blockIdx.x * 4 + threadIdx.y;   // z*Sq + q
    int d = threadIdx.x;
    int z = row >> 9, q = row & 511;
    int b = z >> 3, h = z & 7;
    float m[NSPLIT], l[NSPLIT];
    float mm = -INFINITY;
#pragma unroll
    for (int s = 0; s < NSPLIT; s++) {
        const float* pm = pml + ((size_t)(s * 16 + z) * Sq + q) * 2;
        m[s] = pm[0]; l[s] = pm[1];
        mm = fmaxf(mm, m[s]);
    }
    float lsum = 0.f, o = 0.f;
#pragma unroll
    for (int s = 0; s < NSPLIT; s++) {
        float w = __expf((m[s] - mm) * 0.125f);
        lsum = fmaf(l[s], w, lsum);
        o = fmaf(pout[((size_t)(s * 16 + z) * Sq + q) * DK + d], w, o);
    }
    ctx[(size_t)b * Sq * Dm + (size_t)q * Dm + h * DK + d] = o / lsum;
}

// ---------------- launch ----------------------------------------------------
extern "C" void kernel_launch(void* const* d_in, const int* in_sizes, int n_in,
                              void* d_out, int out_size)
{
    const float* x     = (const float*)d_in[0];
    const int*   mask  = (const int*)d_in[1];
    const float* omega = (const float*)d_in[2];
    const float* Pq    = (const float*)d_in[3];
    const float* Pk    = (const float*)d_in[4];
    const float* Pv    = (const float*)d_in[5];
    const float* Po    = (const float*)d_in[6];
    const float* tab   = (const float*)d_in[7];
    float* out = (float*)d_out;

    static int smem_set = 0;
    if (!smem_set) {
        cudaFuncSetAttribute(attn_part,
            cudaFuncAttributeMaxDynamicSharedMemorySize, ATTN_SMEM);
        smem_set = 1;
    }

    float *p_feat, *p_R, *p_Rcf, *p_qkv, *p_ctx, *p_po, *p_pm, *p_cfp, *p_cf;
    cudaGetSymbolAddress((void**)&p_feat, g_feat);
    cudaGetSymbolAddress((void**)&p_R, g_R);
    cudaGetSymbolAddress((void**)&p_Rcf, g_Rcf);
    cudaGetSymbolAddress((void**)&p_qkv, g_QKV);
    cudaGetSymbolAddress((void**)&p_ctx, g_ctx);
    cudaGetSymbolAddress((void**)&p_po, g_pout);
    cudaGetSymbolAddress((void**)&p_pm, g_pml);
    cudaGetSymbolAddress((void**)&p_cfp, g_cfp);
    cudaGetSymbolAddress((void**)&p_cf, g_cf);

    float* p_Q = p_qkv;
    float* p_K = p_qkv + (size_t)N_TOK * Dm;
    float* p_V = p_qkv + (size_t)2 * N_TOK * Dm;

    dim3 blk(16, 16);

    feat_gemm<<<dim3(2, 96), blk>>>(x, Pq, Pk, Pv, Po, omega, p_feat);
    rowrelu<<<(N_TOK + 4 * Dm) / 8, dim3(32, 8)>>>(p_feat, p_R);

    tversky_qkv<<<dim3(8, 16, 3), blk>>>(p_feat, p_R, tab, p_qkv);

    attn_part<<<dim3(8, 16, NSPLIT), blk, ATTN_SMEM>>>(p_Q, p_K, p_V, mask, p_po, p_pm);
    attn_combine<<<16 * Sq / 4, dim3(64, 4)>>>(p_po, p_pm, p_ctx);

    gemm_split<<<dim3(2, 16, 8), blk>>>(p_ctx, omega, p_cfp);
    add8_relu<<<(N_TOK * Kf / 4) / 256, 256>>>(p_cfp, p_cf, p_Rcf);
    tversky_out<<<dim3(8, 16), blk>>>(p_cf, p_Rcf, p_feat, p_R, tab, out);
}

// round 15
// speedup vs baseline: 1.0502x; 1.0502x over previous
#include <cuda_runtime.h>
#include <math.h>

#define N_TOK 1024
#define Dm 512
#define Kf 128
#define Sq 512
#define DK 64
#define NSPLIT 8
#define ATTN_SMEM ((64 * 132 + 2 * 64 * 68 + 128 * 68) * 4)

// ---------------- scratch ---------------------------------------------------
__device__ float g_feat[(N_TOK + 4 * Dm) * Kf];
__device__ float g_R[N_TOK + 4 * Dm];
__device__ float g_Rcf[N_TOK];
__device__ float g_QKV[3 * N_TOK * Dm];
__device__ float g_ctx[N_TOK * Dm];
__device__ float g_pout[NSPLIT * 16 * Sq * DK];
__device__ float g_pml[NSPLIT * 16 * Sq * 2];
__device__ float g_cfp[8][N_TOK * Kf];
__device__ float g_cf[N_TOK * Kf];

// ---------------- feature GEMM: feat = [x;Pq;Pk;Pv;Po] @ omega --------------
__global__ __launch_bounds__(256) void feat_gemm(
    const float* __restrict__ x,  const float* __restrict__ Pq,
    const float* __restrict__ Pk, const float* __restrict__ Pv,
    const float* __restrict__ Po, const float* __restrict__ omega,
    float* __restrict__ feat)
{
    __shared__ float As[32][36];
    __shared__ float Bs[32][68];
    int tx = threadIdx.x, ty = threadIdx.y;
    int tid = ty * 16 + tx;
    int bm = blockIdx.y * 32, bn = blockIdx.x * 64;

    const float* A;
    int row0;
    if (bm < N_TOK) { A = x; row0 = bm; }
    else {
        int s = (bm - N_TOK) >> 9;
        const float* Ps[4] = {Pq, Pk, Pv, Po};
        A = Ps[s]; row0 = (bm - N_TOK) & 511;
    }

    float acc[2][4] = {};
    for (int k0 = 0; k0 < Dm; k0 += 32) {
#pragma unroll
        for (int l = 0; l < 4; l++) {
            int e = tid + l * 256;
            int i = e >> 5, j = e & 31;
            As[j][i] = A[(size_t)(row0 + i) * Dm + k0 + j];
        }
#pragma unroll
        for (int l = 0; l < 8; l++) {
            int e = tid + l * 256;
            int kk = e >> 6, j = e & 63;
            Bs[kk][j] = omega[(size_t)(k0 + kk) * Kf + bn + j];
        }
        __syncthreads();
#pragma unroll
        for (int k = 0; k < 32; k++) {
            float2 a2 = *(const float2*)&As[k][ty * 2];
            float4 b4 = *(const float4*)&Bs[k][tx * 4];
            acc[0][0] = fmaf(a2.x, b4.x, acc[0][0]);
            acc[0][1] = fmaf(a2.x, b4.y, acc[0][1]);
            acc[0][2] = fmaf(a2.x, b4.z, acc[0][2]);
            acc[0][3] = fmaf(a2.x, b4.w, acc[0][3]);
            acc[1][0] = fmaf(a2.y, b4.x, acc[1][0]);
            acc[1][1] = fmaf(a2.y, b4.y, acc[1][1]);
            acc[1][2] = fmaf(a2.y, b4.z, acc[1][2]);
            acc[1][3] = fmaf(a2.y, b4.w, acc[1][3]);
        }
        __syncthreads();
    }
#pragma unroll
    for (int i = 0; i < 2; i++)
#pragma unroll
        for (int j = 0; j < 4; j++)
            feat[(size_t)(bm + ty * 2 + i) * Kf + bn + tx * 4 + j] = acc[i][j];
}

// ---------------- split-K GEMM (K split 8) ----------------------------------
__global__ __launch_bounds__(256) void gemm_split(
    const float* __restrict__ A, const float* __restrict__ B,
    float* __restrict__ Cp)
{
    __shared__ float As[32][68];
    __shared__ float Bs[32][68];
    int tx = threadIdx.x, ty = threadIdx.y;
    int tid = ty * 16 + tx;
    int bm = blockIdx.y * 64, bn = blockIdx.x * 64;
    int kbase = blockIdx.z * 64;
    float* C = Cp + (size_t)blockIdx.z * N_TOK * Kf;
    float acc[4][4] = {};
    for (int k0 = kbase; k0 < kbase + 64; k0 += 32) {
#pragma unroll
        for (int l = 0; l < 8; l++) {
            int e = tid + l * 256;
            int i = e >> 5, j = e & 31;
            As[j][i] = A[(size_t)(bm + i) * Dm + k0 + j];
        }
#pragma unroll
        for (int l = 0; l < 8; l++) {
            int e = tid + l * 256;
            int kk = e >> 6, j = e & 63;
            Bs[kk][j] = B[(size_t)(k0 + kk) * Kf + bn + j];
        }
        __syncthreads();
#pragma unroll
        for (int k = 0; k < 32; k++) {
            float4 a4 = *(const float4*)&As[k][ty * 4];
            float4 b4 = *(const float4*)&Bs[k][tx * 4];
            float av[4] = {a4.x, a4.y, a4.z, a4.w};
            float bv[4] = {b4.x, b4.y, b4.z, b4.w};
#pragma unroll
            for (int i = 0; i < 4; i++)
#pragma unroll
                for (int j = 0; j < 4; j++)
                    acc[i][j] = fmaf(av[i], bv[j], acc[i][j]);
        }
        __syncthreads();
    }
#pragma unroll
    for (int i = 0; i < 4; i++)
#pragma unroll
        for (int j = 0; j < 4; j++)
            C[(size_t)(bm + ty * 4 + i) * Kf + bn + tx * 4 + j] = acc[i][j];
}

// add 8 split-K partials AND emit row relu-sums (warp == one 128-float row)
__global__ __launch_bounds__(256) void add8_relu(
    const float* __restrict__ Cp, float* __restrict__ C,
    float* __restrict__ Rcf)
{
    int idx = blockIdx.x * 256 + threadIdx.x;
    const size_t n = (size_t)N_TOK * Kf;
    float4 r = ((const float4*)Cp)[idx];
#pragma unroll
    for (int z = 1; z < 8; z++) {
        float4 a = ((const float4*)(Cp + (size_t)z * n))[idx];
        r.x += a.x; r.y += a.y; r.z += a.z; r.w += a.w;
    }
    ((float4*)C)[idx] = r;
    float s = fmaxf(r.x, 0.f) + fmaxf(r.y, 0.f) + fmaxf(r.z, 0.f) + fmaxf(r.w, 0.f);
#pragma unroll
    for (int o = 16; o; o >>= 1) s += __shfl_xor_sync(0xffffffffu, s, o);
    if ((threadIdx.x & 31) == 0) Rcf[idx >> 5] = s;
}

// ---------------- row relu-sums (feat) ---------------------------------------
__global__ __launch_bounds__(256) void rowrelu(const float* __restrict__ f,
                                               float* __restrict__ R)
{
    int row = blockIdx.x * 8 + threadIdx.y;
    int lane = threadIdx.x;
    float4 v = ((const float4*)(f + (size_t)row * Kf))[lane];
    float s = fmaxf(v.x, 0.f) + fmaxf(v.y, 0.f) + fmaxf(v.z, 0.f) + fmaxf(v.w, 0.f);
#pragma unroll
    for (int o = 16; o; o >>= 1) s += __shfl_xor_sync(0xffffffffu, s, o);
    if (lane == 0) R[row] = s;
}

// ---------------- Tversky 64x64 tile, min-trick (no reg cap) -----------------
__device__ __forceinline__ void tversky_tile(
    const float* __restrict__ xf, const float* __restrict__ pf,
    const float* __restrict__ Rx, const float* __restrict__ Rp,
    float th, float al, float be, int bn, int bo,
    float* __restrict__ out, int ldo)
{
    __shared__ float sxa[16][68], sxA[16][68], sxW[16][68];
    __shared__ float spa[16][68], spP[16][68], spW[16][68];
    int tx = threadIdx.x, ty = threadIdx.y;
    int tid = ty * 16 + tx;
    float acc[4][4] = {};
    for (int k0 = 0; k0 < Kf; k0 += 16) {
#pragma unroll
        for (int l = 0; l < 4; l++) {
            int e = tid + l * 256;
            int i = e >> 4, j = e & 15;
            float a = xf[(size_t)(bn + i) * Kf + k0 + j];
            sxa[j][i] = a;
            sxA[j][i] = th * fmaxf(a, 0.f);
            sxW[j][i] = (a > 0.f) ? al : 0.f;
            float p = pf[(size_t)(bo + i) * Kf + k0 + j];
            spa[j][i] = p;
            spP[j][i] = fmaxf(p, 0.f);
            spW[j][i] = (p > 0.f) ? be : 0.f;
        }
        __syncthreads();
#pragma unroll
        for (int k = 0; k < 16; k++) {
            float4 a4 = *(const float4*)&sxa[k][ty * 4];
            float4 A4 = *(const float4*)&sxA[k][ty * 4];
            float4 w4 = *(const float4*)&sxW[k][ty * 4];
            float4 p4 = *(const float4*)&spa[k][tx * 4];
            float4 P4 = *(const float4*)&spP[k][tx * 4];
            float4 v4 = *(const float4*)&spW[k][tx * 4];
            float av[4] = {a4.x, a4.y, a4.z, a4.w};
            float Av[4] = {A4.x, A4.y, A4.z, A4.w};
            float wv[4] = {w4.x, w4.y, w4.z, w4.w};
            float pv[4] = {p4.x, p4.y, p4.z, p4.w};
            float Pv[4] = {P4.x, P4.y, P4.z, P4.w};
            float vv[4] = {v4.x, v4.y, v4.z, v4.w};
#pragma unroll
            for (int i = 0; i < 4; i++)
#pragma unroll
                for (int j = 0; j < 4; j++) {
                    float m = fminf(av[i], pv[j]);
                    float t = acc[i][j];
                    t = fmaf(Av[i], Pv[j], t);
                    t = fmaf(wv[i], m, t);
                    t = fmaf(vv[j], m, t);
                    acc[i][j] = t;
                }
        }
        __syncthreads();
    }
    float rx[4], rp[4];
#pragma unroll
    for (int i = 0; i < 4; i++) rx[i] = al * Rx[bn + ty * 4 + i];
#pragma unroll
    for (int j = 0; j < 4; j++) rp[j] = be * Rp[bo + tx * 4 + j];
#pragma unroll
    for (int i = 0; i < 4; i++)
#pragma unroll
        for (int j = 0; j < 4; j++)
            out[(size_t)(bn + ty * 4 + i) * ldo + bo + tx * 4 + j] =
                acc[i][j] - rx[i] - rp[j];
}

__global__ __launch_bounds__(256) void tversky_qkv(
    const float* __restrict__ feat, const float* __restrict__ R,
    const float* __restrict__ tab, float* __restrict__ qkv)
{
    int z = blockIdx.z;
    const float* pf = feat + (size_t)(N_TOK + z * Dm) * Kf;
    const float* Rp = R + N_TOK + z * Dm;
    const float* t3 = tab + z * 3;
    float* out = qkv + (size_t)z * N_TOK * Dm;
    tversky_tile(feat, pf, R, Rp, t3[0], t3[1], t3[2],
                 blockIdx.y * 64, blockIdx.x * 64, out, Dm);
}

// ---------------- Tversky 32x64 tile for the output projection ---------------
__global__ __launch_bounds__(256) void tversky_out32(
    const float* __restrict__ cf, const float* __restrict__ Rcf,
    const float* __restrict__ feat, const float* __restrict__ R,
    const float* __restrict__ tab, float* __restrict__ out)
{
    __shared__ float sxa[16][36], sxA[16][36], sxW[16][36];
    __shared__ float spa[16][68], spP[16][68], spW[16][68];
    const float* pf = feat + (size_t)(N_TOK + 3 * Dm) * Kf;
    const float* Rp = R + N_TOK + 3 * Dm;
    const float th = tab[9], al = tab[10], be = tab[11];
    int tx = threadIdx.x, ty = threadIdx.y;
    int tid = ty * 16 + tx;
    int bn = blockIdx.y * 32, bo = blockIdx.x * 64;
    float acc[2][4] = {};
    for (int k0 = 0; k0 < Kf; k0 += 16) {
#pragma unroll
        for (int l = 0; l < 2; l++) {      // x planes: 16k x 32 rows
            int e = tid + l * 256;
            int i = e >> 4, j = e & 15;
            float a = cf[(size_t)(bn + i) * Kf + k0 + j];
            sxa[j][i] = a;
            sxA[j][i] = th * fmaxf(a, 0.f);
            sxW[j][i] = (a > 0.f) ? al : 0.f;
        }
#pragma unroll
        for (int l = 0; l < 4; l++) {      // p planes: 16k x 64 rows
            int e = tid + l * 256;
            int i = e >> 4, j = e & 15;
            float p = pf[(size_t)(bo + i) * Kf + k0 + j];
            spa[j][i] = p;
            spP[j][i] = fmaxf(p, 0.f);
            spW[j][i] = (p > 0.f) ? be : 0.f;
        }
        __syncthreads();
#pragma unroll
        for (int k = 0; k < 16; k++) {
            float2 a2 = *(const float2*)&sxa[k][ty * 2];
            float2 A2 = *(const float2*)&sxA[k][ty * 2];
            float2 w2 = *(const float2*)&sxW[k][ty * 2];
            float4 p4 = *(const float4*)&spa[k][tx * 4];
            float4 P4 = *(const float4*)&spP[k][tx * 4];
            float4 v4 = *(const float4*)&spW[k][tx * 4];
            float av[2] = {a2.x, a2.y};
            float Av[2] = {A2.x, A2.y};
            float wv[2] = {w2.x, w2.y};
            float pv[4] = {p4.x, p4.y, p4.z, p4.w};
            float Pv[4] = {P4.x, P4.y, P4.z, P4.w};
            float vv[4] = {v4.x, v4.y, v4.z, v4.w};
#pragma unroll
            for (int i = 0; i < 2; i++)
#pragma unroll
                for (int j = 0; j < 4; j++) {
                    float m = fminf(av[i], pv[j]);
                    float t = acc[i][j];
                    t = fmaf(Av[i], Pv[j], t);
                    t = fmaf(wv[i], m, t);
                    t = fmaf(vv[j], m, t);
                    acc[i][j] = t;
                }
        }
        __syncthreads();
    }
    float rx[2], rp[4];
#pragma unroll
    for (int i = 0; i < 2; i++) rx[i] = al * Rcf[bn + ty * 2 + i];
#pragma unroll
    for (int j = 0; j < 4; j++) rp[j] = be * Rp[bo + tx * 4 + j];
#pragma unroll
    for (int i = 0; i < 2; i++)
#pragma unroll
        for (int j = 0; j < 4; j++)
            out[(size_t)(bn + ty * 2 + i) * Dm + bo + tx * 4 + j] =
                acc[i][j] - rx[i] - rp[j];
}

// ---------------- flash attention v4: q128, 8qx4k, kv-split 8, 2 syncs -------
// smem: Qs[64][132] | Ks[64][68] | Vs[64][68] | Ps[128][68]
__global__ __launch_bounds__(256, 2) void attn_part(
    const float* __restrict__ Q, const float* __restrict__ Km,
    const float* __restrict__ V, const int* __restrict__ mask,
    float* __restrict__ pout, float* __restrict__ pml)
{
    extern __shared__ float smem[];
    float (*Qs)[132] = (float (*)[132])smem;
    float (*Ks)[68]  = (float (*)[68])(smem + 64 * 132);
    float (*Vs)[68]  = (float (*)[68])(smem + 64 * 132 + 64 * 68);
    float (*Ps)[68]  = (float (*)[68])(smem + 64 * 132 + 2 * 64 * 68);
    int z = blockIdx.y;
    int sp = blockIdx.z;
    int b = z >> 3, h = z & 7;
    const float* Qg = Q  + (size_t)b * Sq * Dm + h * DK;
    const float* Kg = Km + (size_t)b * Sq * Dm + h * DK;
    const float* Vg = V  + (size_t)b * Sq * Dm + h * DK;
    const int*   mg = mask + (size_t)b * Sq * Sq;
    int bq = blockIdx.x * 128;
    int bk = sp * 64;
    int tx = threadIdx.x, ty = threadIdx.y;
    int tid = ty * 16 + tx;

#pragma unroll
    for (int l = 0; l < 32; l++) {         // Qs: 128q x 64d
        int e = tid + l * 256;
        int m = e >> 6, d = e & 63;
        Qs[d][m] = Qg[(size_t)(bq + m) * Dm + d];
    }
#pragma unroll
    for (int l = 0; l < 16; l++) {         // Ks[d][k]
        int e = tid + l * 256;
        int kk = e >> 6, d = e & 63;
        Ks[d][kk] = Kg[(size_t)(bk + kk) * Dm + d];
    }
#pragma unroll
    for (int l = 0; l < 16; l++) {         // Vs[k][d]
        int e = tid + l * 256;
        int kk = e >> 6, d = e & 63;
        Vs[kk][d] = Vg[(size_t)(bk + kk) * Dm + d];
    }
    __syncthreads();

    // QK
    float S[8][4] = {};
#pragma unroll
    for (int d = 0; d < 64; d++) {
        float4 qa = *(const float4*)&Qs[d][ty * 8];
        float4 qb = *(const float4*)&Qs[d][ty * 8 + 4];
        float4 k4 = *(const float4*)&Ks[d][tx * 4];
        float qv[8] = {qa.x, qa.y, qa.z, qa.w, qb.x, qb.y, qb.z, qb.w};
        float kv[4] = {k4.x, k4.y, k4.z, k4.w};
#pragma unroll
        for (int i = 0; i < 8; i++)
#pragma unroll
            for (int j = 0; j < 4; j++)
                S[i][j] = fmaf(qv[i], kv[j], S[i][j]);
    }

    // mask
#pragma unroll
    for (int i = 0; i < 8; i++) {
        int row = bq + ty * 8 + i;
        int4 m4 = *(const int4*)&mg[(size_t)row * Sq + bk + tx * 4];
        if (m4.x == 0) S[i][0] = -INFINITY;
        if (m4.y == 0) S[i][1] = -INFINITY;
        if (m4.z == 0) S[i][2] = -INFINITY;
        if (m4.w == 0) S[i][3] = -INFINITY;
    }

    // direct softmax within chunk; (m, l) for combine
    float mr[8], lr[8];
#pragma unroll
    for (int i = 0; i < 8; i++) {
        float c = fmaxf(fmaxf(S[i][0], S[i][1]), fmaxf(S[i][2], S[i][3]));
#pragma unroll
        for (int o = 8; o; o >>= 1)
            c = fmaxf(c, __shfl_xor_sync(0xffffffffu, c, o));
        mr[i] = c;
        float p0 = __expf((S[i][0] - c) * 0.125f);
        float p1 = __expf((S[i][1] - c) * 0.125f);
        float p2 = __expf((S[i][2] - c) * 0.125f);
        float p3 = __expf((S[i][3] - c) * 0.125f);
        S[i][0] = p0; S[i][1] = p1; S[i][2] = p2; S[i][3] = p3;
        float s = p0 + p1 + p2 + p3;
#pragma unroll
        for (int o = 8; o; o >>= 1)
            s += __shfl_xor_sync(0xffffffffu, s, o);
        lr[i] = s;
    }

#pragma unroll
    for (int i = 0; i < 8; i++)
        *(float4*)&Ps[ty * 8 + i][tx * 4] =
            make_float4(S[i][0], S[i][1], S[i][2], S[i][3]);
    __syncthreads();

    // PV: P broadcast, V float4
    float out[8][4] = {};
#pragma unroll
    for (int k = 0; k < 64; k++) {
        float4 v4 = *(const float4*)&Vs[k][tx * 4];
        float vv[4] = {v4.x, v4.y, v4.z, v4.w};
#pragma unroll
        for (int i = 0; i < 8; i++) {
            float p = Ps[ty * 8 + i][k];
#pragma unroll
            for (int j = 0; j < 4; j++)
                out[i][j] = fmaf(p, vv[j], out[i][j]);
        }
    }

    float* po = pout + ((size_t)(sp * 16 + z) * Sq) * DK;
#pragma unroll
    for (int i = 0; i < 8; i++) {
        int row = bq + ty * 8 + i;
        *(float4*)&po[(size_t)row * DK + tx * 4] =
            make_float4(out[i][0], out[i][1], out[i][2], out[i][3]);
        if (tx == 0) {
            float* pm = pml + ((size_t)(sp * 16 + z) * Sq) * 2;
            pm[row * 2] = mr[i]; pm[row * 2 + 1] = lr[i];
        }
    }
}

// combine NSPLIT kv-split partials -> ctx. Block (64, 4).
__global__ __launch_bounds__(256) void attn_combine(
    const float* __restrict__ pout, const float* __restrict__ pml,
    float* __restrict__ ctx)
{
    int row = blockIdx.x * 4 + threadIdx.y;   // z*Sq + q
    int d = threadIdx.x;
    int z = row >> 9, q = row & 511;
    int b = z >> 3, h = z & 7;
    float m[NSPLIT], l[NSPLIT];
    float mm = -INFINITY;
#pragma unroll
    for (int s = 0; s < NSPLIT; s++) {
        const float* pm = pml + ((size_t)(s * 16 + z) * Sq + q) * 2;
        m[s] = pm[0]; l[s] = pm[1];
        mm = fmaxf(mm, m[s]);
    }
    float lsum = 0.f, o = 0.f;
#pragma unroll
    for (int s = 0; s < NSPLIT; s++) {
        float w = __expf((m[s] - mm) * 0.125f);
        lsum = fmaf(l[s], w, lsum);
        o = fmaf(pout[((size_t)(s * 16 + z) * Sq + q) * DK + d], w, o);
    }
    ctx[(size_t)b * Sq * Dm + (size_t)q * Dm + h * DK + d] = o / lsum;
}

// ---------------- launch ----------------------------------------------------
extern "C" void kernel_launch(void* const* d_in, const int* in_sizes, int n_in,
                              void* d_out, int out_size)
{
    const float* x     = (const float*)d_in[0];
    const int*   mask  = (const int*)d_in[1];
    const float* omega = (const float*)d_in[2];
    const float* Pq    = (const float*)d_in[3];
    const float* Pk    = (const float*)d_in[4];
    const float* Pv    = (const float*)d_in[5];
    const float* Po    = (const float*)d_in[6];
    const float* tab   = (const float*)d_in[7];
    float* out = (float*)d_out;

    static int smem_set = 0;
    if (!smem_set) {
        cudaFuncSetAttribute(attn_part,
            cudaFuncAttributeMaxDynamicSharedMemorySize, ATTN_SMEM);
        smem_set = 1;
    }

    float *p_feat, *p_R, *p_Rcf, *p_qkv, *p_ctx, *p_po, *p_pm, *p_cfp, *p_cf;
    cudaGetSymbolAddress((void**)&p_feat, g_feat);
    cudaGetSymbolAddress((void**)&p_R, g_R);
    cudaGetSymbolAddress((void**)&p_Rcf, g_Rcf);
    cudaGetSymbolAddress((void**)&p_qkv, g_QKV);
    cudaGetSymbolAddress((void**)&p_ctx, g_ctx);
    cudaGetSymbolAddress((void**)&p_po, g_pout);
    cudaGetSymbolAddress((void**)&p_pm, g_pml);
    cudaGetSymbolAddress((void**)&p_cfp, g_cfp);
    cudaGetSymbolAddress((void**)&p_cf, g_cf);

    float* p_Q = p_qkv;
    float* p_K = p_qkv + (size_t)N_TOK * Dm;
    float* p_V = p_qkv + (size_t)2 * N_TOK * Dm;

    dim3 blk(16, 16);

    feat_gemm<<<dim3(2, 96), blk>>>(x, Pq, Pk, Pv, Po, omega, p_feat);
    rowrelu<<<(N_TOK + 4 * Dm) / 8, dim3(32, 8)>>>(p_feat, p_R);

    tversky_qkv<<<dim3(8, 16, 3), blk>>>(p_feat, p_R, tab, p_qkv);

    attn_part<<<dim3(4, 16, NSPLIT), blk, ATTN_SMEM>>>(p_Q, p_K, p_V, mask, p_po, p_pm);
    attn_combine<<<16 * Sq / 4, dim3(64, 4)>>>(p_po, p_pm, p_ctx);

    gemm_split<<<dim3(2, 16, 8), blk>>>(p_ctx, omega, p_cfp);
    add8_relu<<<(N_TOK * Kf / 4) / 256, 256>>>(p_cfp, p_cf, p_Rcf);
    tversky_out32<<<dim3(8, 32), blk>>>(p_cf, p_Rcf, p_feat, p_R, tab, out);
}

// round 16
// speedup vs baseline: 1.0572x; 1.0067x over previous
#include <cuda_runtime.h>
#include <math.h>

#define N_TOK 1024
#define Dm 512
#define Kf 128
#define Sq 512
#define DK 64
#define NSPLIT 8
#define ATTN_SMEM ((64 * 132 + 2 * 64 * 68 + 128 * 68) * 4)

// ---------------- scratch ---------------------------------------------------
__device__ float g_feat[(N_TOK + 4 * Dm) * Kf];
__device__ float g_R[N_TOK + 4 * Dm];
__device__ float g_Rcf[N_TOK];
__device__ float g_QKV[3 * N_TOK * Dm];
__device__ float g_ctx[N_TOK * Dm];
__device__ float g_pout[NSPLIT * 16 * Sq * DK];
__device__ float g_pml[NSPLIT * 16 * Sq * 2];
__device__ float g_cfp[8][N_TOK * Kf];
__device__ float g_cf[N_TOK * Kf];

// ---------------- feature GEMM: feat = [x;Pq;Pk;Pv;Po] @ omega --------------
__global__ __launch_bounds__(256) void feat_gemm(
    const float* __restrict__ x,  const float* __restrict__ Pq,
    const float* __restrict__ Pk, const float* __restrict__ Pv,
    const float* __restrict__ Po, const float* __restrict__ omega,
    float* __restrict__ feat)
{
    __shared__ float As[32][36];
    __shared__ float Bs[32][68];
    int tx = threadIdx.x, ty = threadIdx.y;
    int tid = ty * 16 + tx;
    int bm = blockIdx.y * 32, bn = blockIdx.x * 64;

    const float* A;
    int row0;
    if (bm < N_TOK) { A = x; row0 = bm; }
    else {
        int s = (bm - N_TOK) >> 9;
        const float* Ps[4] = {Pq, Pk, Pv, Po};
        A = Ps[s]; row0 = (bm - N_TOK) & 511;
    }

    float acc[2][4] = {};
    for (int k0 = 0; k0 < Dm; k0 += 32) {
#pragma unroll
        for (int l = 0; l < 4; l++) {
            int e = tid + l * 256;
            int i = e >> 5, j = e & 31;
            As[j][i] = A[(size_t)(row0 + i) * Dm + k0 + j];
        }
#pragma unroll
        for (int l = 0; l < 8; l++) {
            int e = tid + l * 256;
            int kk = e >> 6, j = e & 63;
            Bs[kk][j] = omega[(size_t)(k0 + kk) * Kf + bn + j];
        }
        __syncthreads();
#pragma unroll
        for (int k = 0; k < 32; k++) {
            float2 a2 = *(const float2*)&As[k][ty * 2];
            float4 b4 = *(const float4*)&Bs[k][tx * 4];
            acc[0][0] = fmaf(a2.x, b4.x, acc[0][0]);
            acc[0][1] = fmaf(a2.x, b4.y, acc[0][1]);
            acc[0][2] = fmaf(a2.x, b4.z, acc[0][2]);
            acc[0][3] = fmaf(a2.x, b4.w, acc[0][3]);
            acc[1][0] = fmaf(a2.y, b4.x, acc[1][0]);
            acc[1][1] = fmaf(a2.y, b4.y, acc[1][1]);
            acc[1][2] = fmaf(a2.y, b4.z, acc[1][2]);
            acc[1][3] = fmaf(a2.y, b4.w, acc[1][3]);
        }
        __syncthreads();
    }
#pragma unroll
    for (int i = 0; i < 2; i++)
#pragma unroll
        for (int j = 0; j < 4; j++)
            feat[(size_t)(bm + ty * 2 + i) * Kf + bn + tx * 4 + j] = acc[i][j];
}

// ---------------- split-K GEMM (K split 8) ----------------------------------
__global__ __launch_bounds__(256) void gemm_split(
    const float* __restrict__ A, const float* __restrict__ B,
    float* __restrict__ Cp)
{
    __shared__ float As[32][68];
    __shared__ float Bs[32][68];
    int tx = threadIdx.x, ty = threadIdx.y;
    int tid = ty * 16 + tx;
    int bm = blockIdx.y * 64, bn = blockIdx.x * 64;
    int kbase = blockIdx.z * 64;
    float* C = Cp + (size_t)blockIdx.z * N_TOK * Kf;
    float acc[4][4] = {};
    for (int k0 = kbase; k0 < kbase + 64; k0 += 32) {
#pragma unroll
        for (int l = 0; l < 8; l++) {
            int e = tid + l * 256;
            int i = e >> 5, j = e & 31;
            As[j][i] = A[(size_t)(bm + i) * Dm + k0 + j];
        }
#pragma unroll
        for (int l = 0; l < 8; l++) {
            int e = tid + l * 256;
            int kk = e >> 6, j = e & 63;
            Bs[kk][j] = B[(size_t)(k0 + kk) * Kf + bn + j];
        }
        __syncthreads();
#pragma unroll
        for (int k = 0; k < 32; k++) {
            float4 a4 = *(const float4*)&As[k][ty * 4];
            float4 b4 = *(const float4*)&Bs[k][tx * 4];
            float av[4] = {a4.x, a4.y, a4.z, a4.w};
            float bv[4] = {b4.x, b4.y, b4.z, b4.w};
#pragma unroll
            for (int i = 0; i < 4; i++)
#pragma unroll
                for (int j = 0; j < 4; j++)
                    acc[i][j] = fmaf(av[i], bv[j], acc[i][j]);
        }
        __syncthreads();
    }
#pragma unroll
    for (int i = 0; i < 4; i++)
#pragma unroll
        for (int j = 0; j < 4; j++)
            C[(size_t)(bm + ty * 4 + i) * Kf + bn + tx * 4 + j] = acc[i][j];
}

// add 8 split-K partials AND emit row relu-sums (warp == one 128-float row)
__global__ __launch_bounds__(256) void add8_relu(
    const float* __restrict__ Cp, float* __restrict__ C,
    float* __restrict__ Rcf)
{
    int idx = blockIdx.x * 256 + threadIdx.x;
    const size_t n = (size_t)N_TOK * Kf;
    float4 r = ((const float4*)Cp)[idx];
#pragma unroll
    for (int z = 1; z < 8; z++) {
        float4 a = ((const float4*)(Cp + (size_t)z * n))[idx];
        r.x += a.x; r.y += a.y; r.z += a.z; r.w += a.w;
    }
    ((float4*)C)[idx] = r;
    float s = fmaxf(r.x, 0.f) + fmaxf(r.y, 0.f) + fmaxf(r.z, 0.f) + fmaxf(r.w, 0.f);
#pragma unroll
    for (int o = 16; o; o >>= 1) s += __shfl_xor_sync(0xffffffffu, s, o);
    if ((threadIdx.x & 31) == 0) Rcf[idx >> 5] = s;
}

// ---------------- row relu-sums (feat) ---------------------------------------
__global__ __launch_bounds__(256) void rowrelu(const float* __restrict__ f,
                                               float* __restrict__ R)
{
    int row = blockIdx.x * 8 + threadIdx.y;
    int lane = threadIdx.x;
    float4 v = ((const float4*)(f + (size_t)row * Kf))[lane];
    float s = fmaxf(v.x, 0.f) + fmaxf(v.y, 0.f) + fmaxf(v.z, 0.f) + fmaxf(v.w, 0.f);
#pragma unroll
    for (int o = 16; o; o >>= 1) s += __shfl_xor_sync(0xffffffffu, s, o);
    if (lane == 0) R[row] = s;
}

// ---------------- Tversky 64x64 tile, min-trick, double-buffered loads -------
__device__ __forceinline__ void tversky_tile(
    const float* __restrict__ xf, const float* __restrict__ pf,
    const float* __restrict__ Rx, const float* __restrict__ Rp,
    float th, float al, float be, int bn, int bo,
    float* __restrict__ out, int ldo)
{
    __shared__ float sxa[16][68], sxA[16][68], sxW[16][68];
    __shared__ float spa[16][68], spP[16][68], spW[16][68];
    int tx = threadIdx.x, ty = threadIdx.y;
    int tid = ty * 16 + tx;
    int fi = tid >> 4, fj = tid & 15;          // row 0..15 base, k 0..15
    float acc[4][4] = {};

    // stage chunk 0
    float ax[4], px[4];
#pragma unroll
    for (int l = 0; l < 4; l++) {
        int i = fi + l * 16;
        ax[l] = xf[(size_t)(bn + i) * Kf + fj];
        px[l] = pf[(size_t)(bo + i) * Kf + fj];
    }

    for (int c = 0; c < 8; c++) {
        // STS staged chunk
#pragma unroll
        for (int l = 0; l < 4; l++) {
            int i = fi + l * 16;
            float a = ax[l];
            sxa[fj][i] = a;
            sxA[fj][i] = th * fmaxf(a, 0.f);
            sxW[fj][i] = (a > 0.f) ? al : 0.f;
            float p = px[l];
            spa[fj][i] = p;
            spP[fj][i] = fmaxf(p, 0.f);
            spW[fj][i] = (p > 0.f) ? be : 0.f;
        }
        __syncthreads();
        // prefetch next chunk (overlaps compute below)
        if (c < 7) {
            int k0n = (c + 1) * 16;
#pragma unroll
            for (int l = 0; l < 4; l++) {
                int i = fi + l * 16;
                ax[l] = xf[(size_t)(bn + i) * Kf + k0n + fj];
                px[l] = pf[(size_t)(bo + i) * Kf + k0n + fj];
            }
        }
#pragma unroll
        for (int k = 0; k < 16; k++) {
            float4 a4 = *(const float4*)&sxa[k][ty * 4];
            float4 A4 = *(const float4*)&sxA[k][ty * 4];
            float4 w4 = *(const float4*)&sxW[k][ty * 4];
            float4 p4 = *(const float4*)&spa[k][tx * 4];
            float4 P4 = *(const float4*)&spP[k][tx * 4];
            float4 v4 = *(const float4*)&spW[k][tx * 4];
            float av[4] = {a4.x, a4.y, a4.z, a4.w};
            float Av[4] = {A4.x, A4.y, A4.z, A4.w};
            float wv[4] = {w4.x, w4.y, w4.z, w4.w};
            float pv[4] = {p4.x, p4.y, p4.z, p4.w};
            float Pv[4] = {P4.x, P4.y, P4.z, P4.w};
            float vv[4] = {v4.x, v4.y, v4.z, v4.w};
#pragma unroll
            for (int i = 0; i < 4; i++)
#pragma unroll
                for (int j = 0; j < 4; j++) {
                    float m = fminf(av[i], pv[j]);
                    float t = acc[i][j];
                    t = fmaf(Av[i], Pv[j], t);
                    t = fmaf(wv[i], m, t);
                    t = fmaf(vv[j], m, t);
                    acc[i][j] = t;
                }
        }
        __syncthreads();
    }
    float rx[4], rp[4];
#pragma unroll
    for (int i = 0; i < 4; i++) rx[i] = al * Rx[bn + ty * 4 + i];
#pragma unroll
    for (int j = 0; j < 4; j++) rp[j] = be * Rp[bo + tx * 4 + j];
#pragma unroll
    for (int i = 0; i < 4; i++)
#pragma unroll
        for (int j = 0; j < 4; j++)
            out[(size_t)(bn + ty * 4 + i) * ldo + bo + tx * 4 + j] =
                acc[i][j] - rx[i] - rp[j];
}

__global__ __launch_bounds__(256) void tversky_qkv(
    const float* __restrict__ feat, const float* __restrict__ R,
    const float* __restrict__ tab, float* __restrict__ qkv)
{
    int z = blockIdx.z;
    const float* pf = feat + (size_t)(N_TOK + z * Dm) * Kf;
    const float* Rp = R + N_TOK + z * Dm;
    const float* t3 = tab + z * 3;
    float* out = qkv + (size_t)z * N_TOK * Dm;
    tversky_tile(feat, pf, R, Rp, t3[0], t3[1], t3[2],
                 blockIdx.y * 64, blockIdx.x * 64, out, Dm);
}

__global__ __launch_bounds__(256) void tversky_out(
    const float* __restrict__ cf, const float* __restrict__ Rcf,
    const float* __restrict__ feat, const float* __restrict__ R,
    const float* __restrict__ tab, float* __restrict__ out)
{
    const float* pf = feat + (size_t)(N_TOK + 3 * Dm) * Kf;
    const float* Rp = R + N_TOK + 3 * Dm;
    tversky_tile(cf, pf, Rcf, Rp, tab[9], tab[10], tab[11],
                 blockIdx.y * 64, blockIdx.x * 64, out, Dm);
}

// ---------------- flash attention v4: q128, 8qx4k, kv-split 8, 2 syncs -------
// smem: Qs[64][132] | Ks[64][68] | Vs[64][68] | Ps[128][68]
__global__ __launch_bounds__(256, 2) void attn_part(
    const float* __restrict__ Q, const float* __restrict__ Km,
    const float* __restrict__ V, const int* __restrict__ mask,
    float* __restrict__ pout, float* __restrict__ pml)
{
    extern __shared__ float smem[];
    float (*Qs)[132] = (float (*)[132])smem;
    float (*Ks)[68]  = (float (*)[68])(smem + 64 * 132);
    float (*Vs)[68]  = (float (*)[68])(smem + 64 * 132 + 64 * 68);
    float (*Ps)[68]  = (float (*)[68])(smem + 64 * 132 + 2 * 64 * 68);
    int z = blockIdx.y;
    int sp = blockIdx.z;
    int b = z >> 3, h = z & 7;
    const float* Qg = Q  + (size_t)b * Sq * Dm + h * DK;
    const float* Kg = Km + (size_t)b * Sq * Dm + h * DK;
    const float* Vg = V  + (size_t)b * Sq * Dm + h * DK;
    const int*   mg = mask + (size_t)b * Sq * Sq;
    int bq = blockIdx.x * 128;
    int bk = sp * 64;
    int tx = threadIdx.x, ty = threadIdx.y;
    int tid = ty * 16 + tx;

#pragma unroll
    for (int l = 0; l < 32; l++) {
        int e = tid + l * 256;
        int m = e >> 6, d = e & 63;
        Qs[d][m] = Qg[(size_t)(bq + m) * Dm + d];
    }
#pragma unroll
    for (int l = 0; l < 16; l++) {
        int e = tid + l * 256;
        int kk = e >> 6, d = e & 63;
        Ks[d][kk] = Kg[(size_t)(bk + kk) * Dm + d];
    }
#pragma unroll
    for (int l = 0; l < 16; l++) {
        int e = tid + l * 256;
        int kk = e >> 6, d = e & 63;
        Vs[kk][d] = Vg[(size_t)(bk + kk) * Dm + d];
    }
    __syncthreads();

    float S[8][4] = {};
#pragma unroll
    for (int d = 0; d < 64; d++) {
        float4 qa = *(const float4*)&Qs[d][ty * 8];
        float4 qb = *(const float4*)&Qs[d][ty * 8 + 4];
        float4 k4 = *(const float4*)&Ks[d][tx * 4];
        float qv[8] = {qa.x, qa.y, qa.z, qa.w, qb.x, qb.y, qb.z, qb.w};
        float kv[4] = {k4.x, k4.y, k4.z, k4.w};
#pragma unroll
        for (int i = 0; i < 8; i++)
#pragma unroll
            for (int j = 0; j < 4; j++)
                S[i][j] = fmaf(qv[i], kv[j], S[i][j]);
    }

#pragma unroll
    for (int i = 0; i < 8; i++) {
        int row = bq + ty * 8 + i;
        int4 m4 = *(const int4*)&mg[(size_t)row * Sq + bk + tx * 4];
        if (m4.x == 0) S[i][0] = -INFINITY;
        if (m4.y == 0) S[i][1] = -INFINITY;
        if (m4.z == 0) S[i][2] = -INFINITY;
        if (m4.w == 0) S[i][3] = -INFINITY;
    }

    float mr[8], lr[8];
#pragma unroll
    for (int i = 0; i < 8; i++) {
        float c = fmaxf(fmaxf(S[i][0], S[i][1]), fmaxf(S[i][2], S[i][3]));
#pragma unroll
        for (int o = 8; o; o >>= 1)
            c = fmaxf(c, __shfl_xor_sync(0xffffffffu, c, o));
        mr[i] = c;
        float p0 = __expf((S[i][0] - c) * 0.125f);
        float p1 = __expf((S[i][1] - c) * 0.125f);
        float p2 = __expf((S[i][2] - c) * 0.125f);
        float p3 = __expf((S[i][3] - c) * 0.125f);
        S[i][0] = p0; S[i][1] = p1; S[i][2] = p2; S[i][3] = p3;
        float s = p0 + p1 + p2 + p3;
#pragma unroll
        for (int o = 8; o; o >>= 1)
            s += __shfl_xor_sync(0xffffffffu, s, o);
        lr[i] = s;
    }

#pragma unroll
    for (int i = 0; i < 8; i++)
        *(float4*)&Ps[ty * 8 + i][tx * 4] =
            make_float4(S[i][0], S[i][1], S[i][2], S[i][3]);
    __syncthreads();

    float out[8][4] = {};
#pragma unroll
    for (int k = 0; k < 64; k++) {
        float4 v4 = *(const float4*)&Vs[k][tx * 4];
        float vv[4] = {v4.x, v4.y, v4.z, v4.w};
#pragma unroll
        for (int i = 0; i < 8; i++) {
            float p = Ps[ty * 8 + i][k];
#pragma unroll
            for (int j = 0; j < 4; j++)
                out[i][j] = fmaf(p, vv[j], out[i][j]);
        }
    }

    float* po = pout + ((size_t)(sp * 16 + z) * Sq) * DK;
#pragma unroll
    for (int i = 0; i < 8; i++) {
        int row = bq + ty * 8 + i;
        *(float4*)&po[(size_t)row * DK + tx * 4] =
            make_float4(out[i][0], out[i][1], out[i][2], out[i][3]);
        if (tx == 0) {
            float* pm = pml + ((size_t)(sp * 16 + z) * Sq) * 2;
            pm[row * 2] = mr[i]; pm[row * 2 + 1] = lr[i];
        }
    }
}

// combine NSPLIT kv-split partials -> ctx. Block (64, 4).
__global__ __launch_bounds__(256) void attn_combine(
    const float* __restrict__ pout, const float* __restrict__ pml,
    float* __restrict__ ctx)
{
    int row = blockIdx.x * 4 + threadIdx.y;
    int d = threadIdx.x;
    int z = row >> 9, q = row & 511;
    int b = z >> 3, h = z & 7;
    float m[NSPLIT], l[NSPLIT];
    float mm = -INFINITY;
#pragma unroll
    for (int s = 0; s < NSPLIT; s++) {
        const float* pm = pml + ((size_t)(s * 16 + z) * Sq + q) * 2;
        m[s] = pm[0]; l[s] = pm[1];
        mm = fmaxf(mm, m[s]);
    }
    float lsum = 0.f, o = 0.f;
#pragma unroll
    for (int s = 0; s < NSPLIT; s++) {
        float w = __expf((m[s] - mm) * 0.125f);
        lsum = fmaf(l[s], w, lsum);
        o = fmaf(pout[((size_t)(s * 16 + z) * Sq + q) * DK + d], w, o);
    }
    ctx[(size_t)b * Sq * Dm + (size_t)q * Dm + h * DK + d] = o / lsum;
}

// ---------------- launch ----------------------------------------------------
extern "C" void kernel_launch(void* const* d_in, const int* in_sizes, int n_in,
                              void* d_out, int out_size)
{
    const float* x     = (const float*)d_in[0];
    const int*   mask  = (const int*)d_in[1];
    const float* omega = (const float*)d_in[2];
    const float* Pq    = (const float*)d_in[3];
    const float* Pk    = (const float*)d_in[4];
    const float* Pv    = (const float*)d_in[5];
    const float* Po    = (const float*)d_in[6];
    const float* tab   = (const float*)d_in[7];
    float* out = (float*)d_out;

    static int smem_set = 0;
    if (!smem_set) {
        cudaFuncSetAttribute(attn_part,
            cudaFuncAttributeMaxDynamicSharedMemorySize, ATTN_SMEM);
        smem_set = 1;
    }

    float *p_feat, *p_R, *p_Rcf, *p_qkv, *p_ctx, *p_po, *p_pm, *p_cfp, *p_cf;
    cudaGetSymbolAddress((void**)&p_feat, g_feat);
    cudaGetSymbolAddress((void**)&p_R, g_R);
    cudaGetSymbolAddress((void**)&p_Rcf, g_Rcf);
    cudaGetSymbolAddress((void**)&p_qkv, g_QKV);
    cudaGetSymbolAddress((void**)&p_ctx, g_ctx);
    cudaGetSymbolAddress((void**)&p_po, g_pout);
    cudaGetSymbolAddress((void**)&p_pm, g_pml);
    cudaGetSymbolAddress((void**)&p_cfp, g_cfp);
    cudaGetSymbolAddress((void**)&p_cf, g_cf);

    float* p_Q = p_qkv;
    float* p_K = p_qkv + (size_t)N_TOK * Dm;
    float* p_V = p_qkv + (size_t)2 * N_TOK * Dm;

    dim3 blk(16, 16);

    feat_gemm<<<dim3(2, 96), blk>>>(x, Pq, Pk, Pv, Po, omega, p_feat);
    rowrelu<<<(N_TOK + 4 * Dm) / 8, dim3(32, 8)>>>(p_feat, p_R);

    tversky_qkv<<<dim3(8, 16, 3), blk>>>(p_feat, p_R, tab, p_qkv);

    attn_part<<<dim3(4, 16, NSPLIT), blk, ATTN_SMEM>>>(p_Q, p_K, p_V, mask, p_po, p_pm);
    attn_combine<<<16 * Sq / 4, dim3(64, 4)>>>(p_po, p_pm, p_ctx);

    gemm_split<<<dim3(2, 16, 8), blk>>>(p_ctx, omega, p_cfp);
    add8_relu<<<(N_TOK * Kf / 4) / 256, 256>>>(p_cfp, p_cf, p_Rcf);
    tversky_out<<<dim3(8, 16), blk>>>(p_cf, p_Rcf, p_feat, p_R, tab, out);
}

// round 17
// speedup vs baseline: 1.1972x; 1.1324x over previous
#include <cuda_runtime.h>
#include <math.h>

#define N_TOK 1024
#define Dm 512
#define Kf 128
#define Sq 512
#define DK 64
#define NSPLIT 8
#define ATTN_SMEM ((128 * 68 + 64 * 68 + 64 * 68 + 128 * 68) * 4)

// ---------------- scratch ---------------------------------------------------
__device__ float g_feat[(N_TOK + 4 * Dm) * Kf];
__device__ float g_R[N_TOK + 4 * Dm];
__device__ float g_Rcf[N_TOK];
__device__ float g_QKV[3 * N_TOK * Dm];
__device__ float g_ctx[N_TOK * Dm];
__device__ float g_pout[NSPLIT * 16 * Sq * DK];
__device__ float g_pml[NSPLIT * 16 * Sq * 2];
__device__ float g_cfp[8][N_TOK * Kf];
__device__ float g_cf[N_TOK * Kf];

// ---------------- tf32 helpers ----------------------------------------------
__device__ __forceinline__ float to_tf32(float x) {
    unsigned r;
    asm("cvt.rna.tf32.f32 %0, %1;" : "=r"(r) : "f"(x));
    return __uint_as_float(r);
}
__device__ __forceinline__ void mma_tf32(
    float& c0, float& c1, float& c2, float& c3,
    float a0, float a1, float a2, float a3, float b0, float b1)
{
    asm volatile(
        "mma.sync.aligned.m16n8k8.row.col.f32.tf32.tf32.f32 "
        "{%0,%1,%2,%3}, {%4,%5,%6,%7}, {%8,%9}, {%0,%1,%2,%3};"
        : "+f"(c0), "+f"(c1), "+f"(c2), "+f"(c3)
        : "r"(__float_as_uint(a0)), "r"(__float_as_uint(a1)),
          "r"(__float_as_uint(a2)), "r"(__float_as_uint(a3)),
          "r"(__float_as_uint(b0)), "r"(__float_as_uint(b1)));
}

// ---------------- feature GEMM: feat = [x;Pq;Pk;Pv;Po] @ omega --------------
__global__ __launch_bounds__(256) void feat_gemm(
    const float* __restrict__ x,  const float* __restrict__ Pq,
    const float* __restrict__ Pk, const float* __restrict__ Pv,
    const float* __restrict__ Po, const float* __restrict__ omega,
    float* __restrict__ feat)
{
    __shared__ float As[32][36];
    __shared__ float Bs[32][68];
    int tx = threadIdx.x, ty = threadIdx.y;
    int tid = ty * 16 + tx;
    int bm = blockIdx.y * 32, bn = blockIdx.x * 64;

    const float* A;
    int row0;
    if (bm < N_TOK) { A = x; row0 = bm; }
    else {
        int s = (bm - N_TOK) >> 9;
        const float* Ps[4] = {Pq, Pk, Pv, Po};
        A = Ps[s]; row0 = (bm - N_TOK) & 511;
    }

    float acc[2][4] = {};
    for (int k0 = 0; k0 < Dm; k0 += 32) {
#pragma unroll
        for (int l = 0; l < 4; l++) {
            int e = tid + l * 256;
            int i = e >> 5, j = e & 31;
            As[j][i] = A[(size_t)(row0 + i) * Dm + k0 + j];
        }
#pragma unroll
        for (int l = 0; l < 8; l++) {
            int e = tid + l * 256;
            int kk = e >> 6, j = e & 63;
            Bs[kk][j] = omega[(size_t)(k0 + kk) * Kf + bn + j];
        }
        __syncthreads();
#pragma unroll
        for (int k = 0; k < 32; k++) {
            float2 a2 = *(const float2*)&As[k][ty * 2];
            float4 b4 = *(const float4*)&Bs[k][tx * 4];
            acc[0][0] = fmaf(a2.x, b4.x, acc[0][0]);
            acc[0][1] = fmaf(a2.x, b4.y, acc[0][1]);
            acc[0][2] = fmaf(a2.x, b4.z, acc[0][2]);
            acc[0][3] = fmaf(a2.x, b4.w, acc[0][3]);
            acc[1][0] = fmaf(a2.y, b4.x, acc[1][0]);
            acc[1][1] = fmaf(a2.y, b4.y, acc[1][1]);
            acc[1][2] = fmaf(a2.y, b4.z, acc[1][2]);
            acc[1][3] = fmaf(a2.y, b4.w, acc[1][3]);
        }
        __syncthreads();
    }
#pragma unroll
    for (int i = 0; i < 2; i++)
#pragma unroll
        for (int j = 0; j < 4; j++)
            feat[(size_t)(bm + ty * 2 + i) * Kf + bn + tx * 4 + j] = acc[i][j];
}

// ---------------- split-K GEMM (K split 8) ----------------------------------
__global__ __launch_bounds__(256) void gemm_split(
    const float* __restrict__ A, const float* __restrict__ B,
    float* __restrict__ Cp)
{
    __shared__ float As[32][68];
    __shared__ float Bs[32][68];
    int tx = threadIdx.x, ty = threadIdx.y;
    int tid = ty * 16 + tx;
    int bm = blockIdx.y * 64, bn = blockIdx.x * 64;
    int kbase = blockIdx.z * 64;
    float* C = Cp + (size_t)blockIdx.z * N_TOK * Kf;
    float acc[4][4] = {};
    for (int k0 = kbase; k0 < kbase + 64; k0 += 32) {
#pragma unroll
        for (int l = 0; l < 8; l++) {
            int e = tid + l * 256;
            int i = e >> 5, j = e & 31;
            As[j][i] = A[(size_t)(bm + i) * Dm + k0 + j];
        }
#pragma unroll
        for (int l = 0; l < 8; l++) {
            int e = tid + l * 256;
            int kk = e >> 6, j = e & 63;
            Bs[kk][j] = B[(size_t)(k0 + kk) * Kf + bn + j];
        }
        __syncthreads();
#pragma unroll
        for (int k = 0; k < 32; k++) {
            float4 a4 = *(const float4*)&As[k][ty * 4];
            float4 b4 = *(const float4*)&Bs[k][tx * 4];
            float av[4] = {a4.x, a4.y, a4.z, a4.w};
            float bv[4] = {b4.x, b4.y, b4.z, b4.w};
#pragma unroll
            for (int i = 0; i < 4; i++)
#pragma unroll
                for (int j = 0; j < 4; j++)
                    acc[i][j] = fmaf(av[i], bv[j], acc[i][j]);
        }
        __syncthreads();
    }
#pragma unroll
    for (int i = 0; i < 4; i++)
#pragma unroll
        for (int j = 0; j < 4; j++)
            C[(size_t)(bm + ty * 4 + i) * Kf + bn + tx * 4 + j] = acc[i][j];
}

// add 8 split-K partials AND emit row relu-sums (warp == one 128-float row)
__global__ __launch_bounds__(256) void add8_relu(
    const float* __restrict__ Cp, float* __restrict__ C,
    float* __restrict__ Rcf)
{
    int idx = blockIdx.x * 256 + threadIdx.x;
    const size_t n = (size_t)N_TOK * Kf;
    float4 r = ((const float4*)Cp)[idx];
#pragma unroll
    for (int z = 1; z < 8; z++) {
        float4 a = ((const float4*)(Cp + (size_t)z * n))[idx];
        r.x += a.x; r.y += a.y; r.z += a.z; r.w += a.w;
    }
    ((float4*)C)[idx] = r;
    float s = fmaxf(r.x, 0.f) + fmaxf(r.y, 0.f) + fmaxf(r.z, 0.f) + fmaxf(r.w, 0.f);
#pragma unroll
    for (int o = 16; o; o >>= 1) s += __shfl_xor_sync(0xffffffffu, s, o);
    if ((threadIdx.x & 31) == 0) Rcf[idx >> 5] = s;
}

// ---------------- row relu-sums (feat) ---------------------------------------
__global__ __launch_bounds__(256) void rowrelu(const float* __restrict__ f,
                                               float* __restrict__ R)
{
    int row = blockIdx.x * 8 + threadIdx.y;
    int lane = threadIdx.x;
    float4 v = ((const float4*)(f + (size_t)row * Kf))[lane];
    float s = fmaxf(v.x, 0.f) + fmaxf(v.y, 0.f) + fmaxf(v.z, 0.f) + fmaxf(v.w, 0.f);
#pragma unroll
    for (int o = 16; o; o >>= 1) s += __shfl_xor_sync(0xffffffffu, s, o);
    if (lane == 0) R[row] = s;
}

// ---------------- Tversky 64x64 tile, min-trick (R13 plain) ------------------
__device__ __forceinline__ void tversky_tile(
    const float* __restrict__ xf, const float* __restrict__ pf,
    const float* __restrict__ Rx, const float* __restrict__ Rp,
    float th, float al, float be, int bn, int bo,
    float* __restrict__ out, int ldo)
{
    __shared__ float sxa[16][68], sxA[16][68], sxW[16][68];
    __shared__ float spa[16][68], spP[16][68], spW[16][68];
    int tx = threadIdx.x, ty = threadIdx.y;
    int tid = ty * 16 + tx;
    float acc[4][4] = {};
    for (int k0 = 0; k0 < Kf; k0 += 16) {
#pragma unroll
        for (int l = 0; l < 4; l++) {
            int e = tid + l * 256;
            int i = e >> 4, j = e & 15;
            float a = xf[(size_t)(bn + i) * Kf + k0 + j];
            sxa[j][i] = a;
            sxA[j][i] = th * fmaxf(a, 0.f);
            sxW[j][i] = (a > 0.f) ? al : 0.f;
            float p = pf[(size_t)(bo + i) * Kf + k0 + j];
            spa[j][i] = p;
            spP[j][i] = fmaxf(p, 0.f);
            spW[j][i] = (p > 0.f) ? be : 0.f;
        }
        __syncthreads();
#pragma unroll
        for (int k = 0; k < 16; k++) {
            float4 a4 = *(const float4*)&sxa[k][ty * 4];
            float4 A4 = *(const float4*)&sxA[k][ty * 4];
            float4 w4 = *(const float4*)&sxW[k][ty * 4];
            float4 p4 = *(const float4*)&spa[k][tx * 4];
            float4 P4 = *(const float4*)&spP[k][tx * 4];
            float4 v4 = *(const float4*)&spW[k][tx * 4];
            float av[4] = {a4.x, a4.y, a4.z, a4.w};
            float Av[4] = {A4.x, A4.y, A4.z, A4.w};
            float wv[4] = {w4.x, w4.y, w4.z, w4.w};
            float pv[4] = {p4.x, p4.y, p4.z, p4.w};
            float Pv[4] = {P4.x, P4.y, P4.z, P4.w};
            float vv[4] = {v4.x, v4.y, v4.z, v4.w};
#pragma unroll
            for (int i = 0; i < 4; i++)
#pragma unroll
                for (int j = 0; j < 4; j++) {
                    float m = fminf(av[i], pv[j]);
                    float t = acc[i][j];
                    t = fmaf(Av[i], Pv[j], t);
                    t = fmaf(wv[i], m, t);
                    t = fmaf(vv[j], m, t);
                    acc[i][j] = t;
                }
        }
        __syncthreads();
    }
    float rx[4], rp[4];
#pragma unroll
    for (int i = 0; i < 4; i++) rx[i] = al * Rx[bn + ty * 4 + i];
#pragma unroll
    for (int j = 0; j < 4; j++) rp[j] = be * Rp[bo + tx * 4 + j];
#pragma unroll
    for (int i = 0; i < 4; i++)
#pragma unroll
        for (int j = 0; j < 4; j++)
            out[(size_t)(bn + ty * 4 + i) * ldo + bo + tx * 4 + j] =
                acc[i][j] - rx[i] - rp[j];
}

__global__ __launch_bounds__(256) void tversky_qkv(
    const float* __restrict__ feat, const float* __restrict__ R,
    const float* __restrict__ tab, float* __restrict__ qkv)
{
    int z = blockIdx.z;
    const float* pf = feat + (size_t)(N_TOK + z * Dm) * Kf;
    const float* Rp = R + N_TOK + z * Dm;
    const float* t3 = tab + z * 3;
    float* out = qkv + (size_t)z * N_TOK * Dm;
    tversky_tile(feat, pf, R, Rp, t3[0], t3[1], t3[2],
                 blockIdx.y * 64, blockIdx.x * 64, out, Dm);
}

__global__ __launch_bounds__(256) void tversky_out(
    const float* __restrict__ cf, const float* __restrict__ Rcf,
    const float* __restrict__ feat, const float* __restrict__ R,
    const float* __restrict__ tab, float* __restrict__ out)
{
    const float* pf = feat + (size_t)(N_TOK + 3 * Dm) * Kf;
    const float* Rp = R + N_TOK + 3 * Dm;
    tversky_tile(cf, pf, Rcf, Rp, tab[9], tab[10], tab[11],
                 blockIdx.y * 64, blockIdx.x * 64, out, Dm);
}

// ---------------- flash attention v5: tf32 tensor-core MMA -------------------
// q-tile 128, kv-split 8 (one 64-k chunk/block). 8 warps; warp w owns rows
// w*16..w*16+15. QK and PV via mma.m16n8k8.tf32. Only ONE block-wide sync.
// smem: Qs[128][68] ([q][d]) | Ks[64][68] ([k][d]) | Vs[64][68] ([d][k]) |
//       Ps[128][68] ([q][k], warp-private rows)
__global__ __launch_bounds__(256, 2) void attn_part(
    const float* __restrict__ Q, const float* __restrict__ Km,
    const float* __restrict__ V, const int* __restrict__ mask,
    float* __restrict__ pout, float* __restrict__ pml)
{
    extern __shared__ float smem[];
    float (*Qs)[68] = (float (*)[68])smem;
    float (*Ks)[68] = (float (*)[68])(smem + 128 * 68);
    float (*Vs)[68] = (float (*)[68])(smem + 128 * 68 + 64 * 68);
    float (*Ps)[68] = (float (*)[68])(smem + 128 * 68 + 2 * 64 * 68);
    int z = blockIdx.y;
    int sp = blockIdx.z;
    int b = z >> 3, h = z & 7;
    const float* Qg = Q  + (size_t)b * Sq * Dm + h * DK;
    const float* Kg = Km + (size_t)b * Sq * Dm + h * DK;
    const float* Vg = V  + (size_t)b * Sq * Dm + h * DK;
    const int*   mg = mask + (size_t)b * Sq * Sq;
    int bq = blockIdx.x * 128;
    int bk = sp * 64;
    int tid = threadIdx.x;
    int w = tid >> 5, lane = tid & 31;
    int quad = lane >> 2, qt = lane & 3;

#pragma unroll
    for (int l = 0; l < 32; l++) {         // Qs[q][d]
        int e = tid + l * 256;
        int m = e >> 6, d = e & 63;
        Qs[m][d] = to_tf32(Qg[(size_t)(bq + m) * Dm + d]);
    }
#pragma unroll
    for (int l = 0; l < 16; l++) {         // Ks[k][d]
        int e = tid + l * 256;
        int kk = e >> 6, d = e & 63;
        Ks[kk][d] = to_tf32(Kg[(size_t)(bk + kk) * Dm + d]);
    }
#pragma unroll
    for (int l = 0; l < 16; l++) {         // Vs[d][k] (transposed)
        int e = tid + l * 256;
        int kk = e >> 6, d = e & 63;
        Vs[d][kk] = to_tf32(Vg[(size_t)(bk + kk) * Dm + d]);
    }
    __syncthreads();                       // the only block-wide sync

    int row0 = w * 16 + quad, row1 = row0 + 8;

    // ---- QK: S[128x64] via 8 d-steps x 8 n-tiles of m16n8k8 ----
    float c[8][4] = {};
#pragma unroll
    for (int s = 0; s < 8; s++) {
        int d0 = s * 8;
        float a0 = Qs[row0][d0 + qt];
        float a1 = Qs[row1][d0 + qt];
        float a2 = Qs[row0][d0 + qt + 4];
        float a3 = Qs[row1][d0 + qt + 4];
#pragma unroll
        for (int j = 0; j < 8; j++) {
            float b0 = Ks[j * 8 + quad][d0 + qt];
            float b1 = Ks[j * 8 + quad][d0 + qt + 4];
            mma_tf32(c[j][0], c[j][1], c[j][2], c[j][3], a0, a1, a2, a3, b0, b1);
        }
    }

    // ---- mask ----
    int r0g = bq + row0, r1g = bq + row1;
#pragma unroll
    for (int j = 0; j < 8; j++) {
        int col = bk + j * 8 + 2 * qt;
        int2 m0 = *(const int2*)&mg[(size_t)r0g * Sq + col];
        int2 m1 = *(const int2*)&mg[(size_t)r1g * Sq + col];
        if (m0.x == 0) c[j][0] = -INFINITY;
        if (m0.y == 0) c[j][1] = -INFINITY;
        if (m1.x == 0) c[j][2] = -INFINITY;
        if (m1.y == 0) c[j][3] = -INFINITY;
    }

    // ---- softmax within chunk (quad reduction over qt lanes) ----
    float m0r = -INFINITY, m1r = -INFINITY;
#pragma unroll
    for (int j = 0; j < 8; j++) {
        m0r = fmaxf(m0r, fmaxf(c[j][0], c[j][1]));
        m1r = fmaxf(m1r, fmaxf(c[j][2], c[j][3]));
    }
#pragma unroll
    for (int o = 1; o <= 2; o <<= 1) {
        m0r = fmaxf(m0r, __shfl_xor_sync(0xffffffffu, m0r, o));
        m1r = fmaxf(m1r, __shfl_xor_sync(0xffffffffu, m1r, o));
    }
    float l0 = 0.f, l1 = 0.f;
#pragma unroll
    for (int j = 0; j < 8; j++) {
        c[j][0] = __expf((c[j][0] - m0r) * 0.125f);
        c[j][1] = __expf((c[j][1] - m0r) * 0.125f);
        c[j][2] = __expf((c[j][2] - m1r) * 0.125f);
        c[j][3] = __expf((c[j][3] - m1r) * 0.125f);
        l0 += c[j][0] + c[j][1];
        l1 += c[j][2] + c[j][3];
    }
#pragma unroll
    for (int o = 1; o <= 2; o <<= 1) {
        l0 += __shfl_xor_sync(0xffffffffu, l0, o);
        l1 += __shfl_xor_sync(0xffffffffu, l1, o);
    }

    // ---- store probs (tf32) into warp-private Ps rows ----
#pragma unroll
    for (int j = 0; j < 8; j++) {
        int col = j * 8 + 2 * qt;
        *(float2*)&Ps[row0][col] = make_float2(to_tf32(c[j][0]), to_tf32(c[j][1]));
        *(float2*)&Ps[row1][col] = make_float2(to_tf32(c[j][2]), to_tf32(c[j][3]));
    }
    __syncwarp();                          // warp-private rows: warp sync only

    // ---- PV: out[128x64] via 8 key-steps x 8 n-tiles ----
    float o[8][4] = {};
#pragma unroll
    for (int s = 0; s < 8; s++) {
        int k0 = s * 8;
        float a0 = Ps[row0][k0 + qt];
        float a1 = Ps[row1][k0 + qt];
        float a2 = Ps[row0][k0 + qt + 4];
        float a3 = Ps[row1][k0 + qt + 4];
#pragma unroll
        for (int j = 0; j < 8; j++) {
            float b0 = Vs[j * 8 + quad][k0 + qt];
            float b1 = Vs[j * 8 + quad][k0 + qt + 4];
            mma_tf32(o[j][0], o[j][1], o[j][2], o[j][3], a0, a1, a2, a3, b0, b1);
        }
    }

    // ---- write unnormalized partials + (m, l) ----
    float* po = pout + ((size_t)(sp * 16 + z) * Sq) * DK;
#pragma unroll
    for (int j = 0; j < 8; j++) {
        int col = j * 8 + 2 * qt;
        *(float2*)&po[(size_t)r0g * DK + col] = make_float2(o[j][0], o[j][1]);
        *(float2*)&po[(size_t)r1g * DK + col] = make_float2(o[j][2], o[j][3]);
    }
    if (qt == 0) {
        float* pm = pml + ((size_t)(sp * 16 + z) * Sq) * 2;
        pm[r0g * 2] = m0r; pm[r0g * 2 + 1] = l0;
        pm[r1g * 2] = m1r; pm[r1g * 2 + 1] = l1;
    }
}

// combine NSPLIT kv-split partials -> ctx. Block (64, 4).
__global__ __launch_bounds__(256) void attn_combine(
    const float* __restrict__ pout, const float* __restrict__ pml,
    float* __restrict__ ctx)
{
    int row = blockIdx.x * 4 + threadIdx.y;
    int d = threadIdx.x;
    int z = row >> 9, q = row & 511;
    int b = z >> 3, h = z & 7;
    float m[NSPLIT], l[NSPLIT];
    float mm = -INFINITY;
#pragma unroll
    for (int s = 0; s < NSPLIT; s++) {
        const float* pm = pml + ((size_t)(s * 16 + z) * Sq + q) * 2;
        m[s] = pm[0]; l[s] = pm[1];
        mm = fmaxf(mm, m[s]);
    }
    float lsum = 0.f, o = 0.f;
#pragma unroll
    for (int s = 0; s < NSPLIT; s++) {
        float w = __expf((m[s] - mm) * 0.125f);
        lsum = fmaf(l[s], w, lsum);
        o = fmaf(pout[((size_t)(s * 16 + z) * Sq + q) * DK + d], w, o);
    }
    ctx[(size_t)b * Sq * Dm + (size_t)q * Dm + h * DK + d] = o / lsum;
}

// ---------------- launch ----------------------------------------------------
extern "C" void kernel_launch(void* const* d_in, const int* in_sizes, int n_in,
                              void* d_out, int out_size)
{
    const float* x     = (const float*)d_in[0];
    const int*   mask  = (const int*)d_in[1];
    const float* omega = (const float*)d_in[2];
    const float* Pq    = (const float*)d_in[3];
    const float* Pk    = (const float*)d_in[4];
    const float* Pv    = (const float*)d_in[5];
    const float* Po    = (const float*)d_in[6];
    const float* tab   = (const float*)d_in[7];
    float* out = (float*)d_out;

    static int smem_set = 0;
    if (!smem_set) {
        cudaFuncSetAttribute(attn_part,
            cudaFuncAttributeMaxDynamicSharedMemorySize, ATTN_SMEM);
        smem_set = 1;
    }

    float *p_feat, *p_R, *p_Rcf, *p_qkv, *p_ctx, *p_po, *p_pm, *p_cfp, *p_cf;
    cudaGetSymbolAddress((void**)&p_feat, g_feat);
    cudaGetSymbolAddress((void**)&p_R, g_R);
    cudaGetSymbolAddress((void**)&p_Rcf, g_Rcf);
    cudaGetSymbolAddress((void**)&p_qkv, g_QKV);
    cudaGetSymbolAddress((void**)&p_ctx, g_ctx);
    cudaGetSymbolAddress((void**)&p_po, g_pout);
    cudaGetSymbolAddress((void**)&p_pm, g_pml);
    cudaGetSymbolAddress((void**)&p_cfp, g_cfp);
    cudaGetSymbolAddress((void**)&p_cf, g_cf);

    float* p_Q = p_qkv;
    float* p_K = p_qkv + (size_t)N_TOK * Dm;
    float* p_V = p_qkv + (size_t)2 * N_TOK * Dm;

    dim3 blk(16, 16);

    feat_gemm<<<dim3(2, 96), blk>>>(x, Pq, Pk, Pv, Po, omega, p_feat);
    rowrelu<<<(N_TOK + 4 * Dm) / 8, dim3(32, 8)>>>(p_feat, p_R);

    tversky_qkv<<<dim3(8, 16, 3), blk>>>(p_feat, p_R, tab, p_qkv);

    attn_part<<<dim3(4, 16, NSPLIT), 256, ATTN_SMEM>>>(p_Q, p_K, p_V, mask, p_po, p_pm);
    attn_combine<<<16 * Sq / 4, dim3(64, 4)>>>(p_po, p_pm, p_ctx);

    gemm_split<<<dim3(2, 16, 8), blk>>>(p_ctx, omega, p_cfp);
    add8_relu<<<(N_TOK * Kf / 4) / 256, 256>>>(p_cfp, p_cf, p_Rcf);
    tversky_out<<<dim3(8, 16), blk>>>(p_cf, p_Rcf, p_feat, p_R, tab, out);
}